// round 1
// baseline (speedup 1.0000x reference)
#include <cuda_runtime.h>

#define F_IN 128
#define FS   64
#define NH   8
#define NMAX 4096

// persistent scratch (no allocations allowed)
__device__ float  g_M[2 * NH][F_IN];   // fused weight: rows 0..7 -> h1, 8..15 -> h2
__device__ float  g_c[2 * NH];         // fused bias (b1 folded into rows 0..7)
__device__ float  g_h[NMAX][2 * NH];   // per-node features [h1(8) | h2(8)]
__device__ double g_s1, g_s2;          // gate sum / sum of squares

__device__ __forceinline__ float sigm(float x) {
    return 1.0f / (1.0f + __expf(-x));
}

// ---------------------------------------------------------------------------
// Kernel P: fold Wlin,W1,blin,b1 into M[16][128], c[16]; zero accumulators.
// ---------------------------------------------------------------------------
__global__ void prep_kernel(const float* __restrict__ Wlin,
                            const float* __restrict__ blin,
                            const float* __restrict__ W1,
                            const float* __restrict__ b1) {
    int tid = threadIdx.x;
    if (tid == 0) { g_s1 = 0.0; g_s2 = 0.0; }
    for (int idx = tid; idx < 2 * NH * F_IN; idx += blockDim.x) {
        int t = idx / F_IN;          // 0..15
        int k = idx % F_IN;
        int hrow = (t < NH) ? t : (t - NH);
        int off  = (t < NH) ? 0 : FS;
        float acc = 0.0f;
        #pragma unroll 8
        for (int f = 0; f < FS; f++)
            acc += W1[hrow * (2 * FS) + off + f] * Wlin[f * F_IN + k];
        g_M[t][k] = acc;
    }
    if (tid < 2 * NH) {
        int t = tid;
        int hrow = (t < NH) ? t : (t - NH);
        int off  = (t < NH) ? 0 : FS;
        float acc = (t < NH) ? b1[t] : 0.0f;
        for (int f = 0; f < FS; f++)
            acc += W1[hrow * (2 * FS) + off + f] * blin[f];
        g_c[t] = acc;
    }
}

// ---------------------------------------------------------------------------
// Kernel H: g_h[n][t] = x[n] . M[t] + c[t].   16 threads per node.
// ---------------------------------------------------------------------------
__global__ void node_kernel(const float* __restrict__ x, int N) {
    __shared__ float Ms[F_IN][2 * NH];   // transposed: conflict-free reads
    __shared__ float cs[2 * NH];
    int tid = threadIdx.x;
    for (int idx = tid; idx < 2 * NH * F_IN; idx += blockDim.x) {
        int t = idx / F_IN, k = idx % F_IN;
        Ms[k][t] = g_M[t][k];
    }
    if (tid < 2 * NH) cs[tid] = g_c[tid];
    __syncthreads();

    int node = blockIdx.x * (blockDim.x / 16) + (tid >> 4);
    int t = tid & 15;
    if (node >= N) return;

    const float4* xr = (const float4*)(x + (size_t)node * F_IN);
    float acc = cs[t];
    #pragma unroll
    for (int k4 = 0; k4 < F_IN / 4; k4++) {
        float4 v = xr[k4];
        acc += v.x * Ms[4 * k4 + 0][t];
        acc += v.y * Ms[4 * k4 + 1][t];
        acc += v.z * Ms[4 * k4 + 2][t];
        acc += v.w * Ms[4 * k4 + 3][t];
    }
    g_h[node][t] = acc;
}

// ---------------------------------------------------------------------------
// Kernel E: per-edge gate + block-reduced sums for variance.
// ---------------------------------------------------------------------------
__global__ void edge_kernel(const int* __restrict__ ei,
                            const float* __restrict__ u,
                            const float* __restrict__ W2,
                            const float* __restrict__ b2,
                            float* __restrict__ gate, int E) {
    int e = blockIdx.x * blockDim.x + threadIdx.x;
    float g = 0.0f;
    if (e < E) {
        int i = ei[e];
        int j = ei[E + e];
        const float4* hi = (const float4*)g_h[i];
        const float4* hj = (const float4*)g_h[j];
        float4 hi0 = hi[0], hi1 = hi[1], hi2 = hi[2], hi3 = hi[3];
        float4 hj0 = hj[0], hj1 = hj[1], hj2 = hj[2], hj3 = hj[3];
        float a1[8] = {hi0.x, hi0.y, hi0.z, hi0.w, hi1.x, hi1.y, hi1.z, hi1.w};
        float a2[8] = {hi2.x, hi2.y, hi2.z, hi2.w, hi3.x, hi3.y, hi3.z, hi3.w};
        float c1[8] = {hj0.x, hj0.y, hj0.z, hj0.w, hj1.x, hj1.y, hj1.z, hj1.w};
        float c2[8] = {hj2.x, hj2.y, hj2.z, hj2.w, hj3.x, hj3.y, hj3.z, hj3.w};

        float b2v = b2[0];
        float sij = b2v, sji = b2v;
        #pragma unroll
        for (int h = 0; h < NH; h++) {
            float w2h = W2[h];
            sij += w2h * sigm(a1[h] + c2[h]);   // h1[i] + h2[j]  (b1 folded)
            sji += w2h * sigm(c1[h] + a2[h]);   // h1[j] + h2[i]
        }
        float w = 0.5f * (sigm(sij) + sigm(sji));

        float uu = u[e];
        // eps = 1 - 1e-4 - 0.9998*u ;  1-eps computed directly (no cancellation)
        float eps     = fmaf(-0.9998f, uu, 0.9999f);
        float onemeps = fmaf( 0.9998f, uu, 0.0001f);
        float logit = __logf(eps) - __logf(onemeps);
        g = sigm(2.0f * (logit + w));
        gate[e] = g;
    }

    // block reduction of (g, g^2)
    float g2 = g * g;
    #pragma unroll
    for (int o = 16; o > 0; o >>= 1) {
        g  += __shfl_down_sync(0xffffffffu, g,  o);
        g2 += __shfl_down_sync(0xffffffffu, g2, o);
    }
    __shared__ float s1[8], s2[8];
    int lane = threadIdx.x & 31, wid = threadIdx.x >> 5;
    if (lane == 0) { s1[wid] = g; s2[wid] = g2; }
    __syncthreads();
    if (threadIdx.x == 0) {
        float a = 0.0f, b = 0.0f;
        int nw = blockDim.x >> 5;
        for (int w = 0; w < nw; w++) { a += s1[w]; b += s2[w]; }
        atomicAdd(&g_s1, (double)a);
        atomicAdd(&g_s2, (double)b);
    }
}

// ---------------------------------------------------------------------------
// Kernel F: unbiased variance -> last output element.
// ---------------------------------------------------------------------------
__global__ void finalize_kernel(float* __restrict__ out, int E, int out_size) {
    double s1 = g_s1, s2 = g_s2;
    double mean = s1 / (double)E;
    double var = (s2 - s1 * mean) / (double)(E - 1);
    out[out_size - 1] = (float)var;
}

extern "C" void kernel_launch(void* const* d_in, const int* in_sizes, int n_in,
                              void* d_out, int out_size) {
    const float* x    = (const float*)d_in[0];   // [N, 128]
    const float* Wlin = (const float*)d_in[1];   // [64, 128]
    const float* blin = (const float*)d_in[2];   // [64]
    const float* W1   = (const float*)d_in[3];   // [8, 128]
    const float* b1   = (const float*)d_in[4];   // [8]
    const float* W2   = (const float*)d_in[5];   // [8]
    const float* b2   = (const float*)d_in[6];   // [1]
    const int*   ei   = (const int*)d_in[7];     // [2, E]
    const float* u    = (const float*)d_in[8];   // [E]

    int N = in_sizes[0] / F_IN;
    int E = in_sizes[8];
    float* out = (float*)d_out;

    prep_kernel<<<1, 256>>>(Wlin, blin, W1, b1);
    node_kernel<<<(N + 15) / 16, 256>>>(x, N);
    edge_kernel<<<(E + 255) / 256, 256>>>(ei, u, W2, b2, out, E);
    finalize_kernel<<<1, 1>>>(out, E, out_size);
}

// round 2
// speedup vs baseline: 1.1440x; 1.1440x over previous
#include <cuda_runtime.h>

#define F_IN 128
#define FS   64
#define NH   8
#define NMAX 4096
#define NBLK 148
#define NTHR 256

// persistent scratch (allocations forbidden)
__device__ float    g_h[NMAX][2 * NH];   // per-node features [h1(8) | h2(8)]
__device__ double   g_s1, g_s2;          // gate sum / sum of squares
__device__ unsigned g_count = 0;         // grid-barrier arrivals
__device__ unsigned g_gen   = 0;         // grid-barrier generation (monotone)

__device__ __forceinline__ float sigm(float x) {
    float e = __expf(-x);
    return __fdividef(1.0f, 1.0f + e);
}
__device__ __forceinline__ float tanh_fast(float x) {
    float r;
    asm("tanh.approx.f32 %0, %1;" : "=f"(r) : "f"(x));
    return r;
}
// sigmoid via tanh.approx: 1 MUFU instead of 2. abs err ~5e-4, used only on
// the inner pair-MLP activations where it attenuates to ~7e-5 on the gate.
__device__ __forceinline__ float sigm_fast(float x) {
    return fmaf(0.5f, tanh_fast(0.5f * x), 0.5f);
}

// sense-reversal grid barrier; safe because grid==NBLK<=#SMs (all co-resident)
__device__ __forceinline__ void grid_barrier() {
    __syncthreads();
    if (threadIdx.x == 0) {
        unsigned my = *(volatile unsigned*)&g_gen;
        __threadfence();
        if (atomicAdd(&g_count, 1u) == NBLK - 1) {
            g_count = 0;
            __threadfence();
            atomicAdd(&g_gen, 1u);
        } else {
            while (*(volatile unsigned*)&g_gen == my) { }
            __threadfence();
        }
    }
    __syncthreads();
}

__global__ void __launch_bounds__(NTHR)
fused_kernel(const float* __restrict__ x,
             const float* __restrict__ Wlin,
             const float* __restrict__ blin,
             const float* __restrict__ W1,
             const float* __restrict__ b1,
             const float* __restrict__ W2,
             const float* __restrict__ b2,
             const int*   __restrict__ ei,
             const float* __restrict__ u,
             float* __restrict__ out,
             int N, int E, int out_size) {
    __shared__ float Ms[F_IN][2 * NH];      // fused weight, transposed
    __shared__ float cs[2 * NH];            // fused bias
    __shared__ float W1s[NH][2 * FS];
    __shared__ float blins[FS];
    __shared__ float w2s[NH];
    __shared__ float b2s;
    __shared__ float r1[NTHR / 32], r2[NTHR / 32];

    const int tid = threadIdx.x;

    // ---- stage small weights into smem; reset accumulators ----
    for (int i = tid; i < NH * 2 * FS; i += NTHR)
        W1s[i / (2 * FS)][i % (2 * FS)] = W1[i];
    for (int i = tid; i < FS; i += NTHR) blins[i] = blin[i];
    if (tid < NH) w2s[tid] = W2[tid];
    if (tid == 0) b2s = b2[0];
    if (blockIdx.x == 0 && tid == 0) { g_s1 = 0.0; g_s2 = 0.0; }
    __syncthreads();

    // ---- phase 1 (per-block, redundant): M = W1 @ Wlin, c = b1 + W1 @ blin ----
    for (int idx = tid; idx < 2 * NH * F_IN; idx += NTHR) {
        int t = idx >> 7;              // 0..15
        int k = idx & (F_IN - 1);
        int hrow = t & (NH - 1);
        int off  = (t < NH) ? 0 : FS;
        float acc = 0.0f;
        #pragma unroll 8
        for (int f = 0; f < FS; f++)
            acc = fmaf(W1s[hrow][off + f], Wlin[f * F_IN + k], acc);
        Ms[k][t] = acc;
    }
    if (tid < 2 * NH) {
        int t = tid, hrow = t & (NH - 1), off = (t < NH) ? 0 : FS;
        float acc = (t < NH) ? b1[t] : 0.0f;
        for (int f = 0; f < FS; f++)
            acc = fmaf(W1s[hrow][off + f], blins[f], acc);
        cs[t] = acc;
    }
    __syncthreads();

    // ---- phase 2: node features. 16 threads per node ----
    const int t = tid & 15;
    for (int nb = blockIdx.x; nb * 16 < N; nb += NBLK) {
        int node = nb * 16 + (tid >> 4);
        if (node < N) {
            const float4* xr = (const float4*)(x + (size_t)node * F_IN);
            float acc = cs[t];
            #pragma unroll
            for (int k4 = 0; k4 < F_IN / 4; k4++) {
                float4 v = xr[k4];
                acc = fmaf(v.x, Ms[4 * k4 + 0][t], acc);
                acc = fmaf(v.y, Ms[4 * k4 + 1][t], acc);
                acc = fmaf(v.z, Ms[4 * k4 + 2][t], acc);
                acc = fmaf(v.w, Ms[4 * k4 + 3][t], acc);
            }
            g_h[node][t] = acc;
        }
    }
    grid_barrier();   // g_h complete & visible

    // ---- phase 3: edges ----
    float w2r[NH];
    #pragma unroll
    for (int h = 0; h < NH; h++) w2r[h] = w2s[h];
    const float b2v = b2s;

    float ls1 = 0.0f, ls2 = 0.0f;
    for (int e = blockIdx.x * NTHR + tid; e < E; e += NBLK * NTHR) {
        int i = ei[e];
        int j = ei[E + e];
        float4 hiA = *(const float4*)&g_h[i][0];
        float4 hiB = *(const float4*)&g_h[i][4];
        float4 hiC = *(const float4*)&g_h[i][8];
        float4 hiD = *(const float4*)&g_h[i][12];
        float4 hjA = *(const float4*)&g_h[j][0];
        float4 hjB = *(const float4*)&g_h[j][4];
        float4 hjC = *(const float4*)&g_h[j][8];
        float4 hjD = *(const float4*)&g_h[j][12];
        float uu = u[e];

        float A1[NH] = {hiA.x, hiA.y, hiA.z, hiA.w, hiB.x, hiB.y, hiB.z, hiB.w};
        float A2[NH] = {hiC.x, hiC.y, hiC.z, hiC.w, hiD.x, hiD.y, hiD.z, hiD.w};
        float C1[NH] = {hjA.x, hjA.y, hjA.z, hjA.w, hjB.x, hjB.y, hjB.z, hjB.w};
        float C2[NH] = {hjC.x, hjC.y, hjC.z, hjC.w, hjD.x, hjD.y, hjD.z, hjD.w};

        float sij = b2v, sji = b2v;
        #pragma unroll
        for (int h = 0; h < NH; h++) {
            sij = fmaf(w2r[h], sigm_fast(A1[h] + C2[h]), sij);
            sji = fmaf(w2r[h], sigm_fast(C1[h] + A2[h]), sji);
        }
        float w = 0.5f * (sigm(sij) + sigm(sji));

        // eps = 0.9999 - 0.9998*u ; 1-eps computed directly (no cancellation)
        float eps     = fmaf(-0.9998f, uu, 0.9999f);
        float onemeps = fmaf( 0.9998f, uu, 0.0001f);
        float logit = __logf(__fdividef(eps, onemeps));
        float g = sigm(2.0f * (logit + w));
        out[e] = g;
        ls1 += g;
        ls2 = fmaf(g, g, ls2);
    }

    // block reduction of (sum, sumsq) then one double atomic per block
    #pragma unroll
    for (int o = 16; o > 0; o >>= 1) {
        ls1 += __shfl_down_sync(0xffffffffu, ls1, o);
        ls2 += __shfl_down_sync(0xffffffffu, ls2, o);
    }
    int lane = tid & 31, wid = tid >> 5;
    if (lane == 0) { r1[wid] = ls1; r2[wid] = ls2; }
    __syncthreads();
    if (tid == 0) {
        float a = 0.0f, b = 0.0f;
        #pragma unroll
        for (int w = 0; w < NTHR / 32; w++) { a += r1[w]; b += r2[w]; }
        atomicAdd(&g_s1, (double)a);
        atomicAdd(&g_s2, (double)b);
    }

    grid_barrier();   // all partial sums landed

    // ---- phase 4: unbiased variance ----
    if (blockIdx.x == 0 && tid == 0) {
        double s1 = atomicAdd(&g_s1, 0.0);   // L2-coherent read
        double s2 = atomicAdd(&g_s2, 0.0);
        double mean = s1 / (double)E;
        out[out_size - 1] = (float)((s2 - s1 * mean) / (double)(E - 1));
    }
}

extern "C" void kernel_launch(void* const* d_in, const int* in_sizes, int n_in,
                              void* d_out, int out_size) {
    const float* x    = (const float*)d_in[0];   // [N, 128]
    const float* Wlin = (const float*)d_in[1];   // [64, 128]
    const float* blin = (const float*)d_in[2];   // [64]
    const float* W1   = (const float*)d_in[3];   // [8, 128]
    const float* b1   = (const float*)d_in[4];   // [8]
    const float* W2   = (const float*)d_in[5];   // [8]
    const float* b2   = (const float*)d_in[6];   // [1]
    const int*   ei   = (const int*)d_in[7];     // [2, E]
    const float* u    = (const float*)d_in[8];   // [E]

    int N = in_sizes[0] / F_IN;
    int E = in_sizes[8];

    fused_kernel<<<NBLK, NTHR>>>(x, Wlin, blin, W1, b1, W2, b2, ei, u,
                                 (float*)d_out, N, E, out_size);
}

// round 3
// speedup vs baseline: 1.3104x; 1.1455x over previous
#include <cuda_runtime.h>

#define F_IN 128
#define FS   64
#define NH   8
#define NMAX 4096
#define NBLK 148
#define NTHR 1024

// persistent scratch (allocations forbidden)
__device__ float    g_h[NMAX][2 * NH];   // per-node features [h1(8) | h2(8)]
__device__ double   g_s1, g_s2;          // gate sum / sum of squares
__device__ unsigned g_count = 0;         // grid-barrier arrivals
__device__ unsigned g_gen   = 0;         // grid-barrier generation (monotone)

__device__ __forceinline__ float tanh_fast(float x) {
    float r;
    asm("tanh.approx.f32 %0, %1;" : "=f"(r) : "f"(x));
    return r;
}
// sigmoid(x) = 0.5*tanh(0.5x)+0.5 : single MUFU op
__device__ __forceinline__ float sigm_fast(float x) {
    return fmaf(0.5f, tanh_fast(0.5f * x), 0.5f);
}

// sense-reversal grid barrier; safe because grid==NBLK<=#SMs (all co-resident)
__device__ __forceinline__ void grid_barrier() {
    __syncthreads();
    if (threadIdx.x == 0) {
        unsigned my = *(volatile unsigned*)&g_gen;
        __threadfence();
        if (atomicAdd(&g_count, 1u) == NBLK - 1) {
            g_count = 0;
            __threadfence();
            atomicAdd(&g_gen, 1u);
        } else {
            while (*(volatile unsigned*)&g_gen == my) { }
            __threadfence();
        }
    }
    __syncthreads();
}

__global__ void __launch_bounds__(NTHR, 1)
fused_kernel(const float* __restrict__ x,
             const float* __restrict__ Wlin,
             const float* __restrict__ blin,
             const float* __restrict__ W1,
             const float* __restrict__ b1,
             const float* __restrict__ W2,
             const float* __restrict__ b2,
             const int*   __restrict__ ei,
             const float* __restrict__ u,
             float* __restrict__ out,
             int N, int E, int out_size) {
    __shared__ float Ms[F_IN][2 * NH];      // fused weight, transposed
    __shared__ float cs[2 * NH];            // fused bias
    __shared__ float W1s[NH][2 * FS];
    __shared__ float blins[FS];
    __shared__ float w2s[NH];
    __shared__ float b2s;
    __shared__ float r1[NTHR / 32], r2[NTHR / 32];

    const int tid  = threadIdx.x;
    const int gtid = blockIdx.x * NTHR + tid;

    // ---- stage small weights into smem; reset accumulators ----
    for (int i = tid; i < NH * 2 * FS; i += NTHR)
        W1s[i / (2 * FS)][i % (2 * FS)] = W1[i];
    if (tid < FS) blins[tid] = blin[tid];
    if (tid < NH) w2s[tid] = W2[tid];
    if (tid == 0) b2s = b2[0];
    if (blockIdx.x == 0 && tid == 0) { g_s1 = 0.0; g_s2 = 0.0; }
    __syncthreads();

    // ---- phase 1 (per-block, redundant): M = W1 @ Wlin, c = b1 + W1 @ blin ----
    for (int idx = tid; idx < 2 * NH * F_IN; idx += NTHR) {
        int t = idx >> 7;              // 0..15
        int k = idx & (F_IN - 1);
        int hrow = t & (NH - 1);
        int off  = (t < NH) ? 0 : FS;
        float acc = 0.0f;
        #pragma unroll 8
        for (int f = 0; f < FS; f++)
            acc = fmaf(W1s[hrow][off + f], Wlin[f * F_IN + k], acc);
        Ms[k][t] = acc;
    }
    if (tid < 2 * NH) {
        int t = tid, hrow = t & (NH - 1), off = (t < NH) ? 0 : FS;
        float acc = (t < NH) ? b1[t] : 0.0f;
        for (int f = 0; f < FS; f++)
            acc = fmaf(W1s[hrow][off + f], blins[f], acc);
        cs[t] = acc;
    }

    // ---- prefetch this thread's edge (independent of g_h) ----
    int   pe_i = 0, pe_j = 0;
    float pe_u = 0.0f;
    const int e0 = gtid;               // NBLK*NTHR = 151552 >= E
    if (e0 < E) { pe_i = ei[e0]; pe_j = ei[E + e0]; pe_u = u[e0]; }

    __syncthreads();

    // ---- phase 2: node features. one node per 16-thread group, grid-wide ----
    {
        int node = gtid >> 4;
        int t = tid & 15;
        if (node < N) {
            const float4* xr = (const float4*)(x + (size_t)node * F_IN);
            float acc = cs[t];
            #pragma unroll
            for (int k4 = 0; k4 < F_IN / 4; k4++) {
                float4 v = xr[k4];
                acc = fmaf(v.x, Ms[4 * k4 + 0][t], acc);
                acc = fmaf(v.y, Ms[4 * k4 + 1][t], acc);
                acc = fmaf(v.z, Ms[4 * k4 + 2][t], acc);
                acc = fmaf(v.w, Ms[4 * k4 + 3][t], acc);
            }
            g_h[node][t] = acc;
        }
    }
    grid_barrier();   // g_h complete & visible

    // ---- phase 3: one edge per thread ----
    float ls1 = 0.0f, ls2 = 0.0f;
    if (e0 < E) {
        const float4* hi = (const float4*)g_h[pe_i];
        const float4* hj = (const float4*)g_h[pe_j];
        float4 hiA = hi[0], hiB = hi[1], hiC = hi[2], hiD = hi[3];
        float4 hjA = hj[0], hjB = hj[1], hjC = hj[2], hjD = hj[3];

        float A1[NH] = {hiA.x, hiA.y, hiA.z, hiA.w, hiB.x, hiB.y, hiB.z, hiB.w};
        float A2[NH] = {hiC.x, hiC.y, hiC.z, hiC.w, hiD.x, hiD.y, hiD.z, hiD.w};
        float C1[NH] = {hjA.x, hjA.y, hjA.z, hjA.w, hjB.x, hjB.y, hjB.z, hjB.w};
        float C2[NH] = {hjC.x, hjC.y, hjC.z, hjC.w, hjD.x, hjD.y, hjD.z, hjD.w};

        float sij = b2s, sji = b2s;
        #pragma unroll
        for (int h = 0; h < NH; h++) {
            float w2h = w2s[h];
            sij = fmaf(w2h, sigm_fast(A1[h] + C2[h]), sij);
            sji = fmaf(w2h, sigm_fast(C1[h] + A2[h]), sji);
        }
        float w = 0.5f * (sigm_fast(sij) + sigm_fast(sji));

        // gate = sigmoid(2*(log(eps/(1-eps)) + w)) = 1/(1 + (onemeps/eps)^2 * e^{-2w})
        float eps     = fmaf(-0.9998f, pe_u, 0.9999f);
        float onemeps = fmaf( 0.9998f, pe_u, 0.0001f);
        float q  = __fdividef(onemeps, eps);
        float a  = q * q * __expf(-2.0f * w);
        float g  = __fdividef(1.0f, 1.0f + a);
        out[e0] = g;
        ls1 = g;
        ls2 = g * g;
    }

    // block reduction of (sum, sumsq) then one double atomic per block
    #pragma unroll
    for (int o = 16; o > 0; o >>= 1) {
        ls1 += __shfl_down_sync(0xffffffffu, ls1, o);
        ls2 += __shfl_down_sync(0xffffffffu, ls2, o);
    }
    int lane = tid & 31, wid = tid >> 5;
    if (lane == 0) { r1[wid] = ls1; r2[wid] = ls2; }
    __syncthreads();
    if (tid < 32) {
        float a = (tid < NTHR / 32) ? r1[tid] : 0.0f;
        float b = (tid < NTHR / 32) ? r2[tid] : 0.0f;
        #pragma unroll
        for (int o = 16; o > 0; o >>= 1) {
            a += __shfl_down_sync(0xffffffffu, a, o);
            b += __shfl_down_sync(0xffffffffu, b, o);
        }
        if (tid == 0) {
            atomicAdd(&g_s1, (double)a);
            atomicAdd(&g_s2, (double)b);
        }
    }

    grid_barrier();   // all partial sums landed

    // ---- phase 4: unbiased variance ----
    if (blockIdx.x == 0 && tid == 0) {
        double s1 = atomicAdd(&g_s1, 0.0);   // L2-coherent read
        double s2 = atomicAdd(&g_s2, 0.0);
        double mean = s1 / (double)E;
        out[out_size - 1] = (float)((s2 - s1 * mean) / (double)(E - 1));
    }
}

extern "C" void kernel_launch(void* const* d_in, const int* in_sizes, int n_in,
                              void* d_out, int out_size) {
    const float* x    = (const float*)d_in[0];   // [N, 128]
    const float* Wlin = (const float*)d_in[1];   // [64, 128]
    const float* blin = (const float*)d_in[2];   // [64]
    const float* W1   = (const float*)d_in[3];   // [8, 128]
    const float* b1   = (const float*)d_in[4];   // [8]
    const float* W2   = (const float*)d_in[5];   // [8]
    const float* b2   = (const float*)d_in[6];   // [1]
    const int*   ei   = (const int*)d_in[7];     // [2, E]
    const float* u    = (const float*)d_in[8];   // [E]

    int N = in_sizes[0] / F_IN;
    int E = in_sizes[8];

    fused_kernel<<<NBLK, NTHR>>>(x, Wlin, blin, W1, b1, W2, b2, ei, u,
                                 (float*)d_out, N, E, out_size);
}

// round 4
// speedup vs baseline: 1.3860x; 1.0577x over previous
#include <cuda_runtime.h>

#define F_IN 128
#define FS   64
#define NH   8
#define NMAX 4096
#define NBLK 148
#define NTHR 1024

// persistent scratch (allocations forbidden)
__device__ float    g_h[NMAX][2 * NH];   // per-node features [h1(8) | h2(8)]
__device__ double   g_s1, g_s2;          // gate sum / sum of squares
__device__ unsigned g_count = 0;         // grid-barrier arrivals
__device__ unsigned g_gen   = 0;         // grid-barrier generation (monotone)
__device__ unsigned g_done  = 0;         // last-block ticket

__device__ __forceinline__ float tanh_fast(float x) {
    float r;
    asm("tanh.approx.f32 %0, %1;" : "=f"(r) : "f"(x));
    return r;
}
// sigmoid(x) = 0.5*tanh(0.5x)+0.5 : single MUFU op
__device__ __forceinline__ float sigm_fast(float x) {
    return fmaf(0.5f, tanh_fast(0.5f * x), 0.5f);
}

// sense-reversal grid barrier; safe because grid==NBLK<=#SMs (all co-resident)
__device__ __forceinline__ void grid_barrier() {
    __threadfence();       // make this thread's global writes visible
    __syncthreads();
    if (threadIdx.x == 0) {
        unsigned my = *(volatile unsigned*)&g_gen;
        if (atomicAdd(&g_count, 1u) == NBLK - 1) {
            g_count = 0;
            __threadfence();
            atomicAdd(&g_gen, 1u);
        } else {
            while (*(volatile unsigned*)&g_gen == my) { }
            __threadfence();
        }
    }
    __syncthreads();
}

__global__ void __launch_bounds__(NTHR, 1)
fused_kernel(const float* __restrict__ x,
             const float* __restrict__ Wlin,
             const float* __restrict__ blin,
             const float* __restrict__ W1,
             const float* __restrict__ b1,
             const float* __restrict__ W2,
             const float* __restrict__ b2,
             const int*   __restrict__ ei,
             const float* __restrict__ u,
             float* __restrict__ out,
             int N, int E, int out_size) {
    __shared__ float WlinS[FS][F_IN];       // 32 KB: staged Wlin
    __shared__ float Ms[F_IN][2 * NH];      // fused weight, transposed
    __shared__ float cs[2 * NH];            // fused bias
    __shared__ float W1s[NH][2 * FS];       // 4 KB
    __shared__ float w2s[NH];
    __shared__ float b2s;
    __shared__ float r1[NTHR / 32], r2[NTHR / 32];

    const int tid  = threadIdx.x;
    const int gtid = blockIdx.x * NTHR + tid;

    // ---- stage Wlin + W1 into smem (coalesced), reset accumulators ----
    {   // 8192 floats = 2048 float4; 1024 threads x 2
        const float4* src = (const float4*)Wlin;
        float4* dst = (float4*)&WlinS[0][0];
        dst[tid]        = src[tid];
        dst[tid + 1024] = src[tid + 1024];
    }
    for (int i = tid; i < NH * 2 * FS; i += NTHR)
        W1s[i / (2 * FS)][i % (2 * FS)] = W1[i];
    if (tid < NH) w2s[tid] = W2[tid];
    if (tid == 0) b2s = b2[0];
    if (blockIdx.x == 0 && tid == 0) { g_s1 = 0.0; g_s2 = 0.0; }

    // ---- prefetch this thread's edge (independent of everything else) ----
    int   pe_i = 0, pe_j = 0;
    float pe_u = 0.0f;
    const int e0 = gtid;               // NBLK*NTHR = 151552 >= E
    if (e0 < E) { pe_i = ei[e0]; pe_j = ei[E + e0]; pe_u = u[e0]; }

    __syncthreads();

    // ---- phase 1 (per-block, redundant, smem-only): M = W1 @ Wlin ----
    #pragma unroll
    for (int r = 0; r < 2; r++) {
        int idx = tid + r * NTHR;          // 0..2047
        int t = idx >> 7;                  // 0..15
        int k = idx & (F_IN - 1);
        int hrow = t & (NH - 1);
        int off  = (t < NH) ? 0 : FS;
        float a0 = 0.f, a1 = 0.f, a2 = 0.f, a3 = 0.f;
        #pragma unroll
        for (int f = 0; f < FS; f += 4) {
            a0 = fmaf(W1s[hrow][off + f + 0], WlinS[f + 0][k], a0);
            a1 = fmaf(W1s[hrow][off + f + 1], WlinS[f + 1][k], a1);
            a2 = fmaf(W1s[hrow][off + f + 2], WlinS[f + 2][k], a2);
            a3 = fmaf(W1s[hrow][off + f + 3], WlinS[f + 3][k], a3);
        }
        Ms[k][t] = (a0 + a1) + (a2 + a3);
    }
    if (tid < 2 * NH) {
        int t = tid, hrow = t & (NH - 1), off = (t < NH) ? 0 : FS;
        float acc = (t < NH) ? b1[t] : 0.0f;
        for (int f = 0; f < FS; f++)
            acc = fmaf(W1s[hrow][off + f], blin[f], acc);
        cs[t] = acc;
    }
    __syncthreads();

    // ---- phase 2: node features, balanced across ALL blocks ----
    // node = blockIdx.x + NBLK * local_group  -> each block handles ~N/NBLK nodes
    {
        int lg = tid >> 4;                 // 0..63
        int t  = tid & 15;
        int node = blockIdx.x + NBLK * lg;
        if (node < N) {
            const float4* xr = (const float4*)(x + (size_t)node * F_IN);
            float b0 = 0.f, b1a = 0.f, b2a = 0.f, b3 = 0.f;
            #pragma unroll
            for (int k4 = 0; k4 < F_IN / 4; k4 += 4) {
                float4 v0 = xr[k4 + 0], v1 = xr[k4 + 1];
                float4 v2 = xr[k4 + 2], v3 = xr[k4 + 3];
                b0 = fmaf(v0.x, Ms[4*k4+ 0][t], b0); b0 = fmaf(v0.y, Ms[4*k4+ 1][t], b0);
                b0 = fmaf(v0.z, Ms[4*k4+ 2][t], b0); b0 = fmaf(v0.w, Ms[4*k4+ 3][t], b0);
                b1a= fmaf(v1.x, Ms[4*k4+ 4][t], b1a);b1a= fmaf(v1.y, Ms[4*k4+ 5][t], b1a);
                b1a= fmaf(v1.z, Ms[4*k4+ 6][t], b1a);b1a= fmaf(v1.w, Ms[4*k4+ 7][t], b1a);
                b2a= fmaf(v2.x, Ms[4*k4+ 8][t], b2a);b2a= fmaf(v2.y, Ms[4*k4+ 9][t], b2a);
                b2a= fmaf(v2.z, Ms[4*k4+10][t], b2a);b2a= fmaf(v2.w, Ms[4*k4+11][t], b2a);
                b3 = fmaf(v3.x, Ms[4*k4+12][t], b3); b3 = fmaf(v3.y, Ms[4*k4+13][t], b3);
                b3 = fmaf(v3.z, Ms[4*k4+14][t], b3); b3 = fmaf(v3.w, Ms[4*k4+15][t], b3);
            }
            g_h[node][t] = cs[t] + ((b0 + b1a) + (b2a + b3));
        }
    }
    grid_barrier();   // g_h complete & visible

    // ---- phase 3: one edge per thread ----
    float ls1 = 0.0f, ls2 = 0.0f;
    if (e0 < E) {
        const float4* hi = (const float4*)g_h[pe_i];
        const float4* hj = (const float4*)g_h[pe_j];
        float4 hiA = hi[0], hiB = hi[1], hiC = hi[2], hiD = hi[3];
        float4 hjA = hj[0], hjB = hj[1], hjC = hj[2], hjD = hj[3];

        float A1[NH] = {hiA.x, hiA.y, hiA.z, hiA.w, hiB.x, hiB.y, hiB.z, hiB.w};
        float A2[NH] = {hiC.x, hiC.y, hiC.z, hiC.w, hiD.x, hiD.y, hiD.z, hiD.w};
        float C1[NH] = {hjA.x, hjA.y, hjA.z, hjA.w, hjB.x, hjB.y, hjB.z, hjB.w};
        float C2[NH] = {hjC.x, hjC.y, hjC.z, hjC.w, hjD.x, hjD.y, hjD.z, hjD.w};

        float sij = b2s, sji = b2s;
        #pragma unroll
        for (int h = 0; h < NH; h++) {
            float w2h = w2s[h];
            sij = fmaf(w2h, sigm_fast(A1[h] + C2[h]), sij);
            sji = fmaf(w2h, sigm_fast(C1[h] + A2[h]), sji);
        }
        float w = 0.5f * (sigm_fast(sij) + sigm_fast(sji));

        // gate = 1/(1 + ((1-eps)/eps)^2 * e^{-2w}),  eps = 0.9999 - 0.9998*u
        float eps     = fmaf(-0.9998f, pe_u, 0.9999f);
        float onemeps = fmaf( 0.9998f, pe_u, 0.0001f);
        float q  = __fdividef(onemeps, eps);
        float a  = q * q * __expf(-2.0f * w);
        float g  = __fdividef(1.0f, 1.0f + a);
        out[e0] = g;
        ls1 = g;
        ls2 = g * g;
    }

    // block reduction of (sum, sumsq)
    #pragma unroll
    for (int o = 16; o > 0; o >>= 1) {
        ls1 += __shfl_down_sync(0xffffffffu, ls1, o);
        ls2 += __shfl_down_sync(0xffffffffu, ls2, o);
    }
    int lane = tid & 31, wid = tid >> 5;
    if (lane == 0) { r1[wid] = ls1; r2[wid] = ls2; }
    __syncthreads();
    if (tid == 0) {
        float a = 0.0f, b = 0.0f;
        #pragma unroll
        for (int w = 0; w < NTHR / 32; w++) { a += r1[w]; b += r2[w]; }
        atomicAdd(&g_s1, (double)a);
        atomicAdd(&g_s2, (double)b);
        __threadfence();
        // last block to finish computes the variance (no second grid barrier)
        if (atomicAdd(&g_done, 1u) == NBLK - 1) {
            g_done = 0;                       // reset for next graph replay
            __threadfence();
            double s1 = atomicAdd(&g_s1, 0.0);
            double s2 = atomicAdd(&g_s2, 0.0);
            double mean = s1 / (double)E;
            out[out_size - 1] = (float)((s2 - s1 * mean) / (double)(E - 1));
        }
    }
}

extern "C" void kernel_launch(void* const* d_in, const int* in_sizes, int n_in,
                              void* d_out, int out_size) {
    const float* x    = (const float*)d_in[0];   // [N, 128]
    const float* Wlin = (const float*)d_in[1];   // [64, 128]
    const float* blin = (const float*)d_in[2];   // [64]
    const float* W1   = (const float*)d_in[3];   // [8, 128]
    const float* b1   = (const float*)d_in[4];   // [8]
    const float* W2   = (const float*)d_in[5];   // [8]
    const float* b2   = (const float*)d_in[6];   // [1]
    const int*   ei   = (const int*)d_in[7];     // [2, E]
    const float* u    = (const float*)d_in[8];   // [E]

    int N = in_sizes[0] / F_IN;
    int E = in_sizes[8];

    fused_kernel<<<NBLK, NTHR>>>(x, Wlin, blin, W1, b1, W2, b2, ei, u,
                                 (float*)d_out, N, E, out_size);
}

// round 5
// speedup vs baseline: 1.5405x; 1.1115x over previous
#include <cuda_runtime.h>
#include <cuda_fp16.h>

#define F_IN 128
#define FS   64
#define NH   8
#define NMAX 4096
#define NBLK 148
#define NTHR 1024

// persistent scratch (allocations forbidden)
__device__ __half   g_hh[NMAX][2 * NH];  // node features fp16: [h1(8) | h2(8)], 32B/row
__device__ double   g_s1, g_s2;          // gate sum / sum of squares
__device__ unsigned g_count = 0;         // grid-barrier arrivals
__device__ unsigned g_gen   = 0;         // grid-barrier generation (monotone)
__device__ unsigned g_done  = 0;         // last-block ticket

__device__ __forceinline__ float tanh_fast(float x) {
    float r;
    asm("tanh.approx.f32 %0, %1;" : "=f"(r) : "f"(x));
    return r;
}
// sigmoid(x) = 0.5*tanh(0.5x)+0.5 : single MUFU op
__device__ __forceinline__ float sigm_fast(float x) {
    return fmaf(0.5f, tanh_fast(0.5f * x), 0.5f);
}

// sense-reversal grid barrier; safe because grid==NBLK<=#SMs (all co-resident)
__device__ __forceinline__ void grid_barrier() {
    __threadfence();
    __syncthreads();
    if (threadIdx.x == 0) {
        unsigned my = *(volatile unsigned*)&g_gen;
        if (atomicAdd(&g_count, 1u) == NBLK - 1) {
            g_count = 0;
            __threadfence();
            atomicAdd(&g_gen, 1u);
        } else {
            while (*(volatile unsigned*)&g_gen == my) { }
            __threadfence();
        }
    }
    __syncthreads();
}

__global__ void __launch_bounds__(NTHR, 1)
fused_kernel(const float* __restrict__ x,
             const float* __restrict__ Wlin,
             const float* __restrict__ blin,
             const float* __restrict__ W1,
             const float* __restrict__ b1,
             const float* __restrict__ W2,
             const float* __restrict__ b2,
             const int*   __restrict__ ei,
             const float* __restrict__ u,
             float* __restrict__ out,
             int N, int E, int out_size) {
    __shared__ float WlinS[FS][F_IN];       // 32 KB: staged Wlin
    __shared__ float Ms[F_IN][2 * NH];      // fused weight, [k][t]
    __shared__ float cs[2 * NH];            // fused bias
    __shared__ float W1s[NH][2 * FS];       // 4 KB
    __shared__ float w2s[NH];
    __shared__ float b2s;
    __shared__ float r1[NTHR / 32], r2[NTHR / 32];

    const int tid  = threadIdx.x;
    const int gtid = blockIdx.x * NTHR + tid;

    // ---- stage Wlin + W1 into smem (coalesced), reset accumulators ----
    {   // 8192 floats = 2048 float4
        const float4* src = (const float4*)Wlin;
        float4* dst = (float4*)&WlinS[0][0];
        dst[tid]        = src[tid];
        dst[tid + 1024] = src[tid + 1024];
    }
    if (tid < NH * 2 * FS) W1s[tid / (2 * FS)][tid % (2 * FS)] = W1[tid];
    if (tid < NH) w2s[tid] = W2[tid];
    if (tid == 0) b2s = b2[0];
    if (blockIdx.x == 0 && tid == 0) { g_s1 = 0.0; g_s2 = 0.0; }

    // ---- prefetch this thread's edge (independent of everything else) ----
    int   pe_i = 0, pe_j = 0;
    float pe_u = 0.0f;
    const int e0 = gtid;               // NBLK*NTHR = 151552 >= E
    if (e0 < E) { pe_i = ei[e0]; pe_j = ei[E + e0]; pe_u = u[e0]; }

    __syncthreads();

    // ---- phase 1 (per-block, redundant): M = W1 @ Wlin, 4-wide k tiles ----
    if (tid < 512) {
        int t  = tid & 15;
        int k4 = tid >> 4;                 // 0..31 -> columns 4*k4..4*k4+3
        int hrow = t & (NH - 1);
        int off  = (t < NH) ? 0 : FS;
        float a0 = 0.f, a1 = 0.f, a2 = 0.f, a3 = 0.f;
        #pragma unroll 8
        for (int f = 0; f < FS; f++) {
            float4 wl = *(const float4*)&WlinS[f][k4 * 4];
            float w1v = W1s[hrow][off + f];
            a0 = fmaf(w1v, wl.x, a0);
            a1 = fmaf(w1v, wl.y, a1);
            a2 = fmaf(w1v, wl.z, a2);
            a3 = fmaf(w1v, wl.w, a3);
        }
        Ms[4 * k4 + 0][t] = a0;
        Ms[4 * k4 + 1][t] = a1;
        Ms[4 * k4 + 2][t] = a2;
        Ms[4 * k4 + 3][t] = a3;
    }
    if (tid >= 512 && tid < 512 + 2 * NH) {
        int t = tid - 512, hrow = t & (NH - 1), off = (t < NH) ? 0 : FS;
        float acc = (t < NH) ? b1[t] : 0.0f;
        for (int f = 0; f < FS; f++)
            acc = fmaf(W1s[hrow][off + f], blin[f], acc);
        cs[t] = acc;
    }
    __syncthreads();

    // ---- phase 2: node features (fp32 compute, fp16 store), balanced ----
    {
        int lg = tid >> 4;                 // 0..63
        int t  = tid & 15;
        int node = blockIdx.x + NBLK * lg;
        bool valid = (node < N);
        float acc = 0.0f;
        if (valid) {
            const float4* xr = (const float4*)(x + (size_t)node * F_IN);
            float b0 = 0.f, b1a = 0.f, b2a = 0.f, b3 = 0.f;
            #pragma unroll
            for (int k4 = 0; k4 < F_IN / 4; k4 += 4) {
                float4 v0 = xr[k4 + 0], v1 = xr[k4 + 1];
                float4 v2 = xr[k4 + 2], v3 = xr[k4 + 3];
                b0 = fmaf(v0.x, Ms[4*k4+ 0][t], b0); b0 = fmaf(v0.y, Ms[4*k4+ 1][t], b0);
                b0 = fmaf(v0.z, Ms[4*k4+ 2][t], b0); b0 = fmaf(v0.w, Ms[4*k4+ 3][t], b0);
                b1a= fmaf(v1.x, Ms[4*k4+ 4][t], b1a);b1a= fmaf(v1.y, Ms[4*k4+ 5][t], b1a);
                b1a= fmaf(v1.z, Ms[4*k4+ 6][t], b1a);b1a= fmaf(v1.w, Ms[4*k4+ 7][t], b1a);
                b2a= fmaf(v2.x, Ms[4*k4+ 8][t], b2a);b2a= fmaf(v2.y, Ms[4*k4+ 9][t], b2a);
                b2a= fmaf(v2.z, Ms[4*k4+10][t], b2a);b2a= fmaf(v2.w, Ms[4*k4+11][t], b2a);
                b3 = fmaf(v3.x, Ms[4*k4+12][t], b3); b3 = fmaf(v3.y, Ms[4*k4+13][t], b3);
                b3 = fmaf(v3.z, Ms[4*k4+14][t], b3); b3 = fmaf(v3.w, Ms[4*k4+15][t], b3);
            }
            acc = cs[t] + ((b0 + b1a) + (b2a + b3));
        }
        // pair (t even, t+1) -> half2 store (shuffle hoisted out of divergence)
        float accN = __shfl_down_sync(0xffffffffu, acc, 1);
        if (valid && !(t & 1))
            ((__half2*)g_hh[node])[t >> 1] = __floats2half2_rn(acc, accN);
    }
    grid_barrier();   // g_hh complete & visible

    // ---- phase 3: one edge per thread (fp16 gather, f32 math) ----
    float ls1 = 0.0f, ls2 = 0.0f;
    if (e0 < E) {
        const uint4* ri = (const uint4*)g_hh[pe_i];
        const uint4* rj = (const uint4*)g_hh[pe_j];
        uint4 i_lo = ri[0], i_hi = ri[1];   // h1_i, h2_i (8 halves each)
        uint4 j_lo = rj[0], j_hi = rj[1];   // h1_j, h2_j

        const unsigned* il = &i_lo.x; const unsigned* ih = &i_hi.x;
        const unsigned* jl = &j_lo.x; const unsigned* jh = &j_hi.x;

        float sij = b2s, sji = b2s;
        #pragma unroll
        for (int q = 0; q < 4; q++) {           // 2 heads per q
            __half2 a = __hadd2(*(const __half2*)&il[q], *(const __half2*)&jh[q]); // h1_i+h2_j
            __half2 c = __hadd2(*(const __half2*)&jl[q], *(const __half2*)&ih[q]); // h1_j+h2_i
            float2 af = __half22float2(a);
            float2 cf = __half22float2(c);
            float w2a = w2s[2 * q], w2b = w2s[2 * q + 1];
            sij = fmaf(w2a, sigm_fast(af.x), sij);
            sij = fmaf(w2b, sigm_fast(af.y), sij);
            sji = fmaf(w2a, sigm_fast(cf.x), sji);
            sji = fmaf(w2b, sigm_fast(cf.y), sji);
        }
        float w = 0.5f * (sigm_fast(sij) + sigm_fast(sji));

        // gate = 1/(1 + ((1-eps)/eps)^2 * e^{-2w}),  eps = 0.9999 - 0.9998*u
        float eps     = fmaf(-0.9998f, pe_u, 0.9999f);
        float onemeps = fmaf( 0.9998f, pe_u, 0.0001f);
        float q  = __fdividef(onemeps, eps);
        float a  = q * q * __expf(-2.0f * w);
        float g  = __fdividef(1.0f, 1.0f + a);
        out[e0] = g;
        ls1 = g;
        ls2 = g * g;
    }

    // block reduction of (sum, sumsq)
    #pragma unroll
    for (int o = 16; o > 0; o >>= 1) {
        ls1 += __shfl_down_sync(0xffffffffu, ls1, o);
        ls2 += __shfl_down_sync(0xffffffffu, ls2, o);
    }
    int lane = tid & 31, wid = tid >> 5;
    if (lane == 0) { r1[wid] = ls1; r2[wid] = ls2; }
    __syncthreads();
    if (tid == 0) {
        float a = 0.0f, b = 0.0f;
        #pragma unroll
        for (int w = 0; w < NTHR / 32; w++) { a += r1[w]; b += r2[w]; }
        atomicAdd(&g_s1, (double)a);
        atomicAdd(&g_s2, (double)b);
        __threadfence();
        // last block to finish computes the variance (no second grid barrier)
        if (atomicAdd(&g_done, 1u) == NBLK - 1) {
            g_done = 0;                       // reset for next graph replay
            __threadfence();
            double s1 = atomicAdd(&g_s1, 0.0);
            double s2 = atomicAdd(&g_s2, 0.0);
            double mean = s1 / (double)E;
            out[out_size - 1] = (float)((s2 - s1 * mean) / (double)(E - 1));
        }
    }
}

extern "C" void kernel_launch(void* const* d_in, const int* in_sizes, int n_in,
                              void* d_out, int out_size) {
    const float* x    = (const float*)d_in[0];   // [N, 128]
    const float* Wlin = (const float*)d_in[1];   // [64, 128]
    const float* blin = (const float*)d_in[2];   // [64]
    const float* W1   = (const float*)d_in[3];   // [8, 128]
    const float* b1   = (const float*)d_in[4];   // [8]
    const float* W2   = (const float*)d_in[5];   // [8]
    const float* b2   = (const float*)d_in[6];   // [1]
    const int*   ei   = (const int*)d_in[7];     // [2, E]
    const float* u    = (const float*)d_in[8];   // [E]

    int N = in_sizes[0] / F_IN;
    int E = in_sizes[8];

    fused_kernel<<<NBLK, NTHR>>>(x, Wlin, blin, W1, b1, W2, b2, ei, u,
                                 (float*)d_out, N, E, out_size);
}